// round 3
// baseline (speedup 1.0000x reference)
#include <cuda_runtime.h>

#define TILE 256
#define NT   128
#define LDA  260   // 64 x [256 rows + pad]; 260*4B % 16B == 0
#define LDB  68

typedef unsigned long long ull;

static __device__ __forceinline__ ull pack2dup(float v) {
    ull r; asm("mov.b64 %0, {%1, %1};" : "=l"(r) : "f"(v)); return r;
}
static __device__ __forceinline__ float2 unpack2(ull v) {
    float2 r; asm("mov.b64 {%0, %1}, %2;" : "=f"(r.x), "=f"(r.y) : "l"(v)); return r;
}
// packed fp32x2 FMA, rn — bit-identical to 2x scalar FFMA
static __device__ __forceinline__ void ffma2(ull& d, ull a, ull b) {
    asm("fma.rn.f32x2 %0, %1, %2, %0;" : "+l"(d) : "l"(a), "l"(b));
}

// branchless 4-step binary search over 15 sorted midpoints -> nearest codebook value
static __device__ __forceinline__ float qlookup(float z, const float* __restrict__ sBnd,
                                                const float* __restrict__ sCb) {
    int idx = (z > sBnd[7]) ? 8 : 0;
    idx += (z > sBnd[idx + 3]) ? 4 : 0;
    idx += (z > sBnd[idx + 1]) ? 2 : 0;
    idx += (z > sBnd[idx]) ? 1 : 0;
    return sCb[idx];
}

__global__ void __launch_bounds__(NT, 2)
tq_kernel(const float* __restrict__ x, const float* __restrict__ cb,
          const float* __restrict__ Rg, float* __restrict__ out, int nrows)
{
    extern __shared__ float smem[];
    float* sA     = smem;                  // [64][LDA] XnT (k-major, row-swizzled); reused as ZhT
    float* sRT    = sA + 64 * LDA;         // [64][LDB]  RT[k][j]
    float* sR     = sRT + 64 * LDB;        // [64][LDB]  R[j][k]
    float* sScale = sR + 64 * LDB;         // [TILE]
    float* sCb    = sScale + TILE;         // [16]
    float* sBnd   = sCb + 16;              // [15]

    const int t = threadIdx.x;
    const int w = t >> 5, l = t & 31;
    const long long row0 = (long long)blockIdx.x * TILE;

    // ---- stage R and R^T ----
    #pragma unroll 4
    for (int i = t; i < 64 * 64; i += NT) {
        int j = i >> 6, k = i & 63;
        float v = Rg[i];
        sR[j * LDB + k]  = v;
        sRT[k * LDB + j] = v;
    }
    if (t < 16) sCb[t] = cb[t];
    if (t < 15) sBnd[t] = 0.5f * (cb[t] + cb[t + 1]);

    // ---- prologue: per pass each warp normalizes 8 rows (4 lanes per row) ----
    {
        const int rl = l >> 2;   // row-in-group 0..7
        const int ch = l & 3;    // 16-float chunk 0..3
        #pragma unroll
        for (int pass = 0; pass < 8; ++pass) {
            int r = pass * 32 + w * 8 + rl;          // local row 0..255
            long long gr = row0 + r;
            if (gr >= nrows) gr = (long long)nrows - 1;
            const float4* xp = (const float4*)(x + gr * 64 + ch * 16);
            float4 v0 = xp[0], v1 = xp[1], v2 = xp[2], v3 = xp[3];
            float ss = v0.x*v0.x + v0.y*v0.y + v0.z*v0.z + v0.w*v0.w
                     + v1.x*v1.x + v1.y*v1.y + v1.z*v1.z + v1.w*v1.w
                     + v2.x*v2.x + v2.y*v2.y + v2.z*v2.z + v2.w*v2.w
                     + v3.x*v3.x + v3.y*v3.y + v3.z*v3.z + v3.w*v3.w;
            ss += __shfl_xor_sync(0xffffffffu, ss, 1);
            ss += __shfl_xor_sync(0xffffffffu, ss, 2);
            float scale = fmaxf(sqrtf(ss), 1e-8f);
            float inv = 1.0f / scale;   // precise division: fp32-accurate z for the argmin
            if (ch == 0) sScale[r] = scale;
            float va[16] = { v0.x, v0.y, v0.z, v0.w, v1.x, v1.y, v1.z, v1.w,
                             v2.x, v2.y, v2.z, v2.w, v3.x, v3.y, v3.z, v3.w };
            #pragma unroll
            for (int m = 0; m < 16; m++) {
                int k = ch * 16 + m;
                sA[k * LDA + (r ^ ((k >> 1) & 28))] = va[m] * inv;   // rot spreads banks: conflict-free
            }
        }
    }
    __syncthreads();

    // ---- mapping: warp w -> rows 64w..64w+63; lane: 16 rows x 8 cols ----
    const int ra = w * 64 + 16 * (l & 3);
    const int ca = 8 * (l >> 2);

    ull acc[8][8];   // [row-pair][col]; f32x2 = rows (ra+2rp, ra+2rp+1)
    #pragma unroll
    for (int i = 0; i < 8; i++)
        #pragma unroll
        for (int c = 0; c < 8; c++) acc[i][c] = 0ull;

    // ---- GEMM1: z[r][j] = sum_k xn[r][k] * R[j][k]  (A = XnT, B = RT) ----
    #pragma unroll 8
    for (int p = 0; p < 64; ++p) {
        const int rot = (p >> 1) & 28;
        const float* ab = sA + p * LDA;
        ulonglong2 q0 = *(const ulonglong2*)(ab + ((ra +  0) ^ rot));
        ulonglong2 q1 = *(const ulonglong2*)(ab + ((ra +  4) ^ rot));
        ulonglong2 q2 = *(const ulonglong2*)(ab + ((ra +  8) ^ rot));
        ulonglong2 q3 = *(const ulonglong2*)(ab + ((ra + 12) ^ rot));
        float4 b0 = *(const float4*)(sRT + p * LDB + ca);
        float4 b1 = *(const float4*)(sRT + p * LDB + ca + 4);
        ull A[8] = { q0.x, q0.y, q1.x, q1.y, q2.x, q2.y, q3.x, q3.y };
        ull B[8] = { pack2dup(b0.x), pack2dup(b0.y), pack2dup(b0.z), pack2dup(b0.w),
                     pack2dup(b1.x), pack2dup(b1.y), pack2dup(b1.z), pack2dup(b1.w) };
        #pragma unroll
        for (int i = 0; i < 8; i++)
            #pragma unroll
            for (int c = 0; c < 8; c++) ffma2(acc[i][c], A[i], B[c]);
    }
    __syncthreads();

    // ---- quantize, write z_hat transposed into sA (ZhT[j][r], same swizzle) ----
    #pragma unroll
    for (int rp = 0; rp < 8; rp++) {
        #pragma unroll
        for (int c = 0; c < 8; c++) {
            float2 z = unpack2(acc[rp][c]);
            float g0 = qlookup(z.x, sBnd, sCb);
            float g1 = qlookup(z.y, sBnd, sCb);
            int j = ca + c;
            int addr = j * LDA + ((ra + 2 * rp) ^ ((j >> 1) & 28));
            *(float2*)(sA + addr) = make_float2(g0, g1);
            acc[rp][c] = 0ull;
        }
    }
    __syncthreads();

    // ---- GEMM2: y[r][k] = sum_j zh[r][j] * R[j][k]  (A = ZhT, B = R) ----
    #pragma unroll 8
    for (int p = 0; p < 64; ++p) {
        const int rot = (p >> 1) & 28;
        const float* ab = sA + p * LDA;
        ulonglong2 q0 = *(const ulonglong2*)(ab + ((ra +  0) ^ rot));
        ulonglong2 q1 = *(const ulonglong2*)(ab + ((ra +  4) ^ rot));
        ulonglong2 q2 = *(const ulonglong2*)(ab + ((ra +  8) ^ rot));
        ulonglong2 q3 = *(const ulonglong2*)(ab + ((ra + 12) ^ rot));
        float4 b0 = *(const float4*)(sR + p * LDB + ca);
        float4 b1 = *(const float4*)(sR + p * LDB + ca + 4);
        ull A[8] = { q0.x, q0.y, q1.x, q1.y, q2.x, q2.y, q3.x, q3.y };
        ull B[8] = { pack2dup(b0.x), pack2dup(b0.y), pack2dup(b0.z), pack2dup(b0.w),
                     pack2dup(b1.x), pack2dup(b1.y), pack2dup(b1.z), pack2dup(b1.w) };
        #pragma unroll
        for (int i = 0; i < 8; i++)
            #pragma unroll
            for (int c = 0; c < 8; c++) ffma2(acc[i][c], A[i], B[c]);
    }

    // ---- rescale + store (two float4 per row, coalesced) ----
    #pragma unroll
    for (int rp = 0; rp < 8; rp++) {
        float2 y0 = unpack2(acc[rp][0]);
        float2 y1 = unpack2(acc[rp][1]);
        float2 y2 = unpack2(acc[rp][2]);
        float2 y3 = unpack2(acc[rp][3]);
        float2 y4 = unpack2(acc[rp][4]);
        float2 y5 = unpack2(acc[rp][5]);
        float2 y6 = unpack2(acc[rp][6]);
        float2 y7 = unpack2(acc[rp][7]);
        int r0 = ra + 2 * rp;
        long long g0 = row0 + r0;
        float s0 = sScale[r0];
        float s1 = sScale[r0 + 1];
        if (g0 < nrows) {
            float4 o0 = make_float4(y0.x*s0, y1.x*s0, y2.x*s0, y3.x*s0);
            float4 o1 = make_float4(y4.x*s0, y5.x*s0, y6.x*s0, y7.x*s0);
            float* op = out + g0 * 64 + ca;
            *(float4*)(op) = o0; *(float4*)(op + 4) = o1;
        }
        if (g0 + 1 < nrows) {
            float4 o0 = make_float4(y0.y*s1, y1.y*s1, y2.y*s1, y3.y*s1);
            float4 o1 = make_float4(y4.y*s1, y5.y*s1, y6.y*s1, y7.y*s1);
            float* op = out + (g0 + 1) * 64 + ca;
            *(float4*)(op) = o0; *(float4*)(op + 4) = o1;
        }
    }
}

extern "C" void kernel_launch(void* const* d_in, const int* in_sizes, int n_in,
                              void* d_out, int out_size)
{
    const float* x  = (const float*)d_in[0];   // [2,32,4096,64] fp32
    const float* cb = (const float*)d_in[1];   // [16] fp32, sorted
    const float* Rg = (const float*)d_in[2];   // [64,64] fp32
    float* out = (float*)d_out;

    int nrows = in_sizes[0] / 64;
    int blocks = (nrows + TILE - 1) / TILE;

    const int smem_bytes = (64 * LDA + 2 * 64 * LDB + TILE + 32) * (int)sizeof(float);
    cudaFuncSetAttribute(tq_kernel, cudaFuncAttributeMaxDynamicSharedMemorySize, smem_bytes);
    tq_kernel<<<blocks, NT, smem_bytes>>>(x, cb, Rg, out, nrows);
}